// round 11
// baseline (speedup 1.0000x reference)
#include <cuda_runtime.h>
#include <cuda_fp16.h>

// ---------------------------------------------------------------------------
// UnfoldindAndAttention: 8 rounds of normalized graph propagation,
// N=50000, D=64, E=1.6M, attention reweighting after round 4.
// Pull-based CSR (grouped by dst): no float atomics, L2-resident.
// R10 resubmit (prior run: broker infra failure, kernel untested).
// R10 = R7 (fp16 agg operand, 8-wide gather, fp32 attention w/ fused rescale)
//       + degree-sorted node permutation: the two nodes sharing a warp are
//         degree-adjacent, removing the E[max(d1,d2)]-E[d] ~10% idle-issue
//         waste in every edge loop. Numerics identical to R7.
// ---------------------------------------------------------------------------

#define NMAX 50048
#define EMAX 1600000
#define DV   16          // 64 floats = 16 float4 (or 16 uint2 fp16) per node row

static __device__ int    g_cnt[NMAX];
static __device__ int    g_cursor[NMAX];
static __device__ int    g_rowptr[NMAX + 1];
static __device__ int    g_bsum[256];
static __device__ int    g_boff[256];
static __device__ int    g_hist[128];          // degree histogram (clamped)
static __device__ int    g_hcur[128];          // bucket cursors (excl. scan)
static __device__ int    g_perm[NMAX];         // nodes sorted by degree
static __device__ int    g_col[EMAX];          // src index per CSR slot
static __device__ float  g_w[EMAX];            // attention weight per CSR slot
static __device__ float  g_rs[NMAX];           // (deg+1)^-0.5
static __device__ float  g_rx[NMAX];           // (deg+1)^-1
static __device__ float4 g_Y[NMAX * DV];       // current Y (fp32)
static __device__ uint2  g_YsA[NMAX * DV];     // rs*Y in fp16 ping
static __device__ uint2  g_YsB[NMAX * DV];     // pong

// -------------------------------------------------------------- setup kernels

__global__ void k_zero(int N) {
    int i = blockIdx.x * 256 + threadIdx.x;
    if (i < N) { g_cnt[i] = 0; g_cursor[i] = 0; }
    if (i < 128) g_hist[i] = 0;
}

__global__ void k_count(const int* __restrict__ dst, int E) {
    int e = blockIdx.x * 256 + threadIdx.x;
    if (e < E) atomicAdd(&g_cnt[dst[e]], 1);
}

// degree histogram (bucket = min(deg,127))
__global__ void k_hist(int N) {
    int i = blockIdx.x * 256 + threadIdx.x;
    if (i < N) atomicAdd(&g_hist[min(g_cnt[i], 127)], 1);
}

// exclusive scan of the 128-bucket histogram -> bucket cursors
__global__ void k_hscan() {
    __shared__ int tmp[128];
    int i = threadIdx.x;
    int h = g_hist[i];
    tmp[i] = h;
    __syncthreads();
    for (int o = 1; o < 128; o <<= 1) {
        int a = (i >= o) ? tmp[i - o] : 0;
        __syncthreads();
        tmp[i] += a;
        __syncthreads();
    }
    g_hcur[i] = tmp[i] - h;   // exclusive
}

// scatter node ids into degree-sorted order
__global__ void k_pscatter(int N) {
    int i = blockIdx.x * 256 + threadIdx.x;
    if (i < N) {
        int b   = min(g_cnt[i], 127);
        int pos = atomicAdd(&g_hcur[b], 1);
        g_perm[pos] = i;
    }
}

// Exclusive block scan (blockDim = 1024). mode 0: cnt -> rowptr (+bsum),
// mode 1: bsum -> boff.
__global__ void k_scan(int mode, int n) {
    const int* in = mode ? g_bsum : g_cnt;
    int* out      = mode ? g_boff : g_rowptr;
    __shared__ int ws[32];
    int g    = blockIdx.x * 1024 + threadIdx.x;
    int lane = threadIdx.x & 31;
    int wid  = threadIdx.x >> 5;
    int v = (g < n) ? in[g] : 0;
    int x = v;
#pragma unroll
    for (int o = 1; o < 32; o <<= 1) {
        int y = __shfl_up_sync(0xFFFFFFFFu, x, o);
        if (lane >= o) x += y;
    }
    if (lane == 31) ws[wid] = x;
    __syncthreads();
    if (wid == 0) {
        int s = ws[lane];
#pragma unroll
        for (int o = 1; o < 32; o <<= 1) {
            int y = __shfl_up_sync(0xFFFFFFFFu, s, o);
            if (lane >= o) s += y;
        }
        ws[lane] = s;
    }
    __syncthreads();
    int boff = wid ? ws[wid - 1] : 0;
    if (g < n) out[g] = boff + x - v;          // exclusive
    if (mode == 0 && threadIdx.x == 0) g_bsum[blockIdx.x] = ws[31];
}

__global__ void k_addoff(int n, int E) {
    int g = blockIdx.x * 1024 + threadIdx.x;
    if (g < n) g_rowptr[g] += g_boff[blockIdx.x];
    if (blockIdx.x == 0 && threadIdx.x == 0) g_rowptr[n] = E;
}

__global__ void k_scatter(const int* __restrict__ src, const int* __restrict__ dst, int E) {
    int e = blockIdx.x * 256 + threadIdx.x;
    if (e < E) {
        int v   = dst[e];
        int off = atomicAdd(&g_cursor[v], 1);
        g_col[g_rowptr[v] + off] = src[e];
    }
}

static __device__ __forceinline__ uint2 pack4(float a, float b, float c, float d) {
    half2 h0 = __floats2half2_rn(a, b);
    half2 h1 = __floats2half2_rn(c, d);
    uint2 r;
    r.x = *(unsigned int*)&h0;
    r.y = *(unsigned int*)&h1;
    return r;
}

// Y0 = X; rs/rx from integer in-degree; YsA = fp16(rs * X)
__global__ void k_init(const float4* __restrict__ X4, int N) {
    int t = blockIdx.x * 256 + threadIdx.x;
    if (t >= N * DV) return;
    int v = t >> 4;
    float deg = (float)g_cnt[v];
    float rs  = 1.0f / sqrtf(deg + 1.0f);
    if ((t & 15) == 0) { g_rs[v] = rs; g_rx[v] = 1.0f / (deg + 1.0f); }
    float4 x = X4[t];
    g_Y[t]   = x;
    g_YsA[t] = pack4(x.x * rs, x.y * rs, x.z * rs, x.w * rs);
}

// -------------------------------------------------------------- propagation

static __device__ __forceinline__ void acc4(float& ax, float& ay, float& az, float& aw,
                                            float w, uint2 q) {
    float2 f0 = __half22float2(*(half2*)&q.x);
    float2 f1 = __half22float2(*(half2*)&q.y);
    ax = fmaf(w, f0.x, ax);
    ay = fmaf(w, f0.y, ay);
    az = fmaf(w, f1.x, az);
    aw = fmaf(w, f1.y, aw);
}

// One propagation step, fused: pull-aggregate + epilogue + next-step operand.
// Half-warp (16 lanes, 4 features each) per node; nodes taken in
// degree-sorted order so warp halves have matching trip counts.
template<bool HAS_W, bool WRITE_YS, bool TO_OUT>
__global__ void __launch_bounds__(256)
k_agg(const float4* __restrict__ X4, float4* __restrict__ outp, int par, int N) {
    int t   = blockIdx.x * 256 + threadIdx.x;
    int grp = t >> 4;
    if (grp >= N) return;
    int v  = g_perm[grp];
    int l  = t & 15;
    int tt = v * DV + l;
    const uint2* __restrict__ Yin = par ? g_YsB : g_YsA;
    uint2* Yso                    = par ? g_YsA : g_YsB;

    int s  = g_rowptr[v];
    int se = g_rowptr[v + 1];
    float ax = 0.f, ay = 0.f, az = 0.f, aw = 0.f;

    for (; s + 8 <= se; s += 8) {
        int c0 = g_col[s],     c1 = g_col[s + 1], c2 = g_col[s + 2], c3 = g_col[s + 3];
        int c4 = g_col[s + 4], c5 = g_col[s + 5], c6 = g_col[s + 6], c7 = g_col[s + 7];
        float w0 = 1.f, w1 = 1.f, w2 = 1.f, w3 = 1.f;
        float w4 = 1.f, w5 = 1.f, w6 = 1.f, w7 = 1.f;
        if (HAS_W) {
            w0 = g_w[s];     w1 = g_w[s + 1]; w2 = g_w[s + 2]; w3 = g_w[s + 3];
            w4 = g_w[s + 4]; w5 = g_w[s + 5]; w6 = g_w[s + 6]; w7 = g_w[s + 7];
        }
        uint2 q0 = Yin[c0 * DV + l];
        uint2 q1 = Yin[c1 * DV + l];
        uint2 q2 = Yin[c2 * DV + l];
        uint2 q3 = Yin[c3 * DV + l];
        uint2 q4 = Yin[c4 * DV + l];
        uint2 q5 = Yin[c5 * DV + l];
        uint2 q6 = Yin[c6 * DV + l];
        uint2 q7 = Yin[c7 * DV + l];
        acc4(ax, ay, az, aw, w0, q0);
        acc4(ax, ay, az, aw, w1, q1);
        acc4(ax, ay, az, aw, w2, q2);
        acc4(ax, ay, az, aw, w3, q3);
        acc4(ax, ay, az, aw, w4, q4);
        acc4(ax, ay, az, aw, w5, q5);
        acc4(ax, ay, az, aw, w6, q6);
        acc4(ax, ay, az, aw, w7, q7);
    }
    for (; s < se; ++s) {
        int c    = g_col[s];
        float wv = HAS_W ? g_w[s] : 1.f;
        acc4(ax, ay, az, aw, wv, Yin[c * DV + l]);
    }

    float rs  = g_rs[v];
    float rx  = g_rx[v];
    float hrs = 0.5f * rs;
    float hrx = 0.5f * rx;
    float4 y = g_Y[tt];
    float4 x = X4[tt];
    float4 yn;
    yn.x = 0.5f * y.x + hrs * ax + hrx * x.x;
    yn.y = 0.5f * y.y + hrs * ay + hrx * x.y;
    yn.z = 0.5f * y.z + hrs * az + hrx * x.z;
    yn.w = 0.5f * y.w + hrs * aw + hrx * x.w;

    if (TO_OUT) outp[tt] = yn; else g_Y[tt] = yn;
    if (WRITE_YS) Yso[tt] = pack4(yn.x * rs, yn.y * rs, yn.z * rs, yn.w * rs);
}

// -------------------------------------------------------------- attention

// Per node (degree-sorted order): Zv in registers, gather Y[src] (fp32),
// 16-lane shfl reduction of |dZ|^2 with the group mask (two nodes share a
// warp; full-warp sync-shfl in this loop would deadlock on unequal trips).
// Lane 0 computes w and the weighted degree. Fused rescale at the end.
__global__ void __launch_bounds__(256)
k_attn(const float4* __restrict__ etas4, int N) {
    int t   = blockIdx.x * 256 + threadIdx.x;
    int grp = t >> 4;
    if (grp >= N) return;
    int v  = g_perm[grp];
    int l  = t & 15;
    int tt = v * DV + l;
    unsigned mask = 0xFFFFu << (threadIdx.x & 16);

    float4 et = etas4[l];
    float4 yv = g_Y[tt];
    float4 zv = make_float4(yv.x * et.x, yv.y * et.y, yv.z * et.z, yv.w * et.w);

    float degw = 0.f;
    int se = g_rowptr[v + 1];
    for (int s = g_rowptr[v]; s < se; ++s) {
        int c     = g_col[s];
        float4 yc = g_Y[c * DV + l];
        float dx = zv.x - yc.x * et.x;
        float dy = zv.y - yc.y * et.y;
        float dz = zv.z - yc.z * et.z;
        float dw = zv.w - yc.w * et.w;
        float p = dx * dx + dy * dy + dz * dz + dw * dw;
        p += __shfl_xor_sync(mask, p, 8);
        p += __shfl_xor_sync(mask, p, 4);
        p += __shfl_xor_sync(mask, p, 2);
        p += __shfl_xor_sync(mask, p, 1);
        if (l == 0) {
            float wv = (p > 2.0f) ? 0.2f : 0.5f / sqrtf(p + 1e-7f);
            g_w[s] = wv;
            degw  += wv;
        }
    }
    // fused rescale: broadcast degw from lane 0 of each 16-lane group
    float deg = __shfl_sync(0xFFFFFFFFu, degw, 0, 16);
    float rs  = 1.0f / sqrtf(deg + 1.0f);
    if (l == 0) { g_rs[v] = rs; g_rx[v] = 1.0f / (deg + 1.0f); }
    g_YsA[tt] = pack4(yv.x * rs, yv.y * rs, yv.z * rs, yv.w * rs);
}

// -------------------------------------------------------------- launcher

extern "C" void kernel_launch(void* const* d_in, const int* in_sizes, int n_in,
                              void* d_out, int out_size) {
    const float4* X4    = (const float4*)d_in[0];
    const float4* etas4 = (const float4*)d_in[1];
    const int*    src   = (const int*)d_in[2];
    const int*    dst   = (const int*)d_in[3];
    float4*       out4  = (float4*)d_out;

    int N = in_sizes[0] / 64;
    int E = in_sizes[2];

    int bN  = (N + 255) / 256;
    int bE  = (E + 255) / 256;
    int NB  = (N + 1023) / 1024;
    int bT  = (N * DV + 255) / 256;

    // ---- CSR build + degree sort ----
    k_zero<<<bN, 256>>>(N);
    k_count<<<bE, 256>>>(dst, E);
    k_hist<<<bN, 256>>>(N);
    k_hscan<<<1, 128>>>();
    k_scan<<<NB, 1024>>>(0, N);
    k_scan<<<1, 1024>>>(1, NB);
    k_addoff<<<NB, 1024>>>(N, E);
    k_pscatter<<<bN, 256>>>(N);
    k_scatter<<<bE, 256>>>(src, dst, E);
    k_init<<<bT, 256>>>(X4, N);

    // ---- steps 0..3: w == 1 ----
    k_agg<false, true,  false><<<bT, 256>>>(X4, out4, 0, N);
    k_agg<false, true,  false><<<bT, 256>>>(X4, out4, 1, N);
    k_agg<false, true,  false><<<bT, 256>>>(X4, out4, 0, N);
    k_agg<false, false, false><<<bT, 256>>>(X4, out4, 1, N);

    // ---- attention after round 4 (rescale fused) ----
    k_attn<<<bT, 256>>>(etas4, N);

    // ---- steps 4..7: attention weights ----
    k_agg<true, true,  false><<<bT, 256>>>(X4, out4, 0, N);
    k_agg<true, true,  false><<<bT, 256>>>(X4, out4, 1, N);
    k_agg<true, true,  false><<<bT, 256>>>(X4, out4, 0, N);
    k_agg<true, false, true ><<<bT, 256>>>(X4, out4, 1, N);
}

// round 12
// speedup vs baseline: 1.0135x; 1.0135x over previous
#include <cuda_runtime.h>
#include <cuda_fp16.h>

// ---------------------------------------------------------------------------
// UnfoldindAndAttention: 8 rounds of normalized graph propagation,
// N=50000, D=64, E=1.6M, attention reweighting after round 4.
// Pull-based CSR (grouped by dst): no float atomics, L2-resident.
// R12 = R7 mainloop EXACTLY (fp16 agg operand, 8-wide gather, fp32
//       attention with fused rescale — best measured: 323.7us)
//       + setup trimmed: rowptr scan is now ONE decoupled-lookback kernel
//         (replaces k_scan x2 + k_addoff). 49 blocks, all co-resident, so
//         the lookback spin cannot deadlock; flags re-zeroed every call.
// ---------------------------------------------------------------------------

#define NMAX 50048
#define EMAX 1600000
#define DV   16          // 64 floats = 16 float4 (or 16 uint2 fp16) per node row

static __device__ int    g_cnt[NMAX];
static __device__ int    g_cursor[NMAX];
static __device__ int    g_rowptr[NMAX + 1];
static __device__ int    g_flag[64];           // lookback: 0=none,1=aggr,2=prefix
static __device__ int    g_aggr[64];           // per-block aggregate
static __device__ int    g_pref[64];           // per-block inclusive prefix
static __device__ int    g_col[EMAX];          // src index per CSR slot
static __device__ float  g_w[EMAX];            // attention weight per CSR slot
static __device__ float  g_rs[NMAX];           // (deg+1)^-0.5
static __device__ float  g_rx[NMAX];           // (deg+1)^-1
static __device__ float4 g_Y[NMAX * DV];       // current Y (fp32)
static __device__ uint2  g_YsA[NMAX * DV];     // rs*Y in fp16 ping
static __device__ uint2  g_YsB[NMAX * DV];     // pong

// -------------------------------------------------------------- setup kernels

__global__ void k_zero(int N) {
    int i = blockIdx.x * 256 + threadIdx.x;
    if (i < N) { g_cnt[i] = 0; g_cursor[i] = 0; }
    if (i < 64) { g_flag[i] = 0; g_aggr[i] = 0; g_pref[i] = 0; }
}

__global__ void k_count(const int* __restrict__ dst, int E) {
    int e = blockIdx.x * 256 + threadIdx.x;
    if (e < E) atomicAdd(&g_cnt[dst[e]], 1);
}

// Single-kernel exclusive scan of g_cnt -> g_rowptr via decoupled lookback.
// blockDim = 1024; gridDim = ceil(N/1024) = 49 <= 64 (all co-resident).
__global__ void k_scanlb(int n, int E) {
    __shared__ int ws[32];
    __shared__ int sprefix;
    int g    = blockIdx.x * 1024 + threadIdx.x;
    int lane = threadIdx.x & 31;
    int wid  = threadIdx.x >> 5;
    int v = (g < n) ? g_cnt[g] : 0;
    int x = v;
#pragma unroll
    for (int o = 1; o < 32; o <<= 1) {
        int y = __shfl_up_sync(0xFFFFFFFFu, x, o);
        if (lane >= o) x += y;
    }
    if (lane == 31) ws[wid] = x;
    __syncthreads();
    if (wid == 0) {
        int s = ws[lane];
#pragma unroll
        for (int o = 1; o < 32; o <<= 1) {
            int y = __shfl_up_sync(0xFFFFFFFFu, s, o);
            if (lane >= o) s += y;
        }
        ws[lane] = s;
    }
    __syncthreads();
    int boff  = wid ? ws[wid - 1] : 0;
    int total = ws[31];

    if (threadIdx.x == 0) {
        int b = blockIdx.x;
        if (b == 0) {
            g_pref[0] = total;
            __threadfence();
            atomicExch(&g_flag[0], 2);
            sprefix = 0;
        } else {
            g_aggr[b] = total;
            __threadfence();
            atomicExch(&g_flag[b], 1);
            int pfx = 0;
            for (int p = b - 1; p >= 0; --p) {
                int f;
                do { f = atomicAdd(&g_flag[p], 0); } while (f == 0);
                if (f == 2) { pfx += atomicAdd(&g_pref[p], 0); break; }
                pfx += atomicAdd(&g_aggr[p], 0);
            }
            g_pref[b] = pfx + total;
            __threadfence();
            atomicExch(&g_flag[b], 2);
            sprefix = pfx;
        }
    }
    __syncthreads();
    if (g < n) g_rowptr[g] = sprefix + boff + x - v;   // exclusive
    if (g == 0) g_rowptr[n] = E;
}

__global__ void k_scatter(const int* __restrict__ src, const int* __restrict__ dst, int E) {
    int e = blockIdx.x * 256 + threadIdx.x;
    if (e < E) {
        int v   = dst[e];
        int off = atomicAdd(&g_cursor[v], 1);
        g_col[g_rowptr[v] + off] = src[e];
    }
}

static __device__ __forceinline__ uint2 pack4(float a, float b, float c, float d) {
    half2 h0 = __floats2half2_rn(a, b);
    half2 h1 = __floats2half2_rn(c, d);
    uint2 r;
    r.x = *(unsigned int*)&h0;
    r.y = *(unsigned int*)&h1;
    return r;
}

// Y0 = X; rs/rx from integer in-degree; YsA = fp16(rs * X)
__global__ void k_init(const float4* __restrict__ X4, int N) {
    int t = blockIdx.x * 256 + threadIdx.x;
    if (t >= N * DV) return;
    int v = t >> 4;
    float deg = (float)g_cnt[v];
    float rs  = 1.0f / sqrtf(deg + 1.0f);
    if ((t & 15) == 0) { g_rs[v] = rs; g_rx[v] = 1.0f / (deg + 1.0f); }
    float4 x = X4[t];
    g_Y[t]   = x;
    g_YsA[t] = pack4(x.x * rs, x.y * rs, x.z * rs, x.w * rs);
}

// -------------------------------------------------------------- propagation

static __device__ __forceinline__ void acc4(float& ax, float& ay, float& az, float& aw,
                                            float w, uint2 q) {
    float2 f0 = __half22float2(*(half2*)&q.x);
    float2 f1 = __half22float2(*(half2*)&q.y);
    ax = fmaf(w, f0.x, ax);
    ay = fmaf(w, f0.y, ay);
    az = fmaf(w, f1.x, az);
    aw = fmaf(w, f1.y, aw);
}

// One propagation step, fused: pull-aggregate + epilogue + next-step operand.
// Half-warp (16 lanes, 4 features each) per node. 8 gathers in flight.
template<bool HAS_W, bool WRITE_YS, bool TO_OUT>
__global__ void __launch_bounds__(256)
k_agg(const float4* __restrict__ X4, float4* __restrict__ outp, int par, int N) {
    int t = blockIdx.x * 256 + threadIdx.x;
    int v = t >> 4;
    if (v >= N) return;
    int l = t & 15;
    const uint2* __restrict__ Yin = par ? g_YsB : g_YsA;
    uint2* Yso                    = par ? g_YsA : g_YsB;

    int s  = g_rowptr[v];
    int se = g_rowptr[v + 1];
    float ax = 0.f, ay = 0.f, az = 0.f, aw = 0.f;

    for (; s + 8 <= se; s += 8) {
        int c0 = g_col[s],     c1 = g_col[s + 1], c2 = g_col[s + 2], c3 = g_col[s + 3];
        int c4 = g_col[s + 4], c5 = g_col[s + 5], c6 = g_col[s + 6], c7 = g_col[s + 7];
        float w0 = 1.f, w1 = 1.f, w2 = 1.f, w3 = 1.f;
        float w4 = 1.f, w5 = 1.f, w6 = 1.f, w7 = 1.f;
        if (HAS_W) {
            w0 = g_w[s];     w1 = g_w[s + 1]; w2 = g_w[s + 2]; w3 = g_w[s + 3];
            w4 = g_w[s + 4]; w5 = g_w[s + 5]; w6 = g_w[s + 6]; w7 = g_w[s + 7];
        }
        uint2 q0 = Yin[c0 * DV + l];
        uint2 q1 = Yin[c1 * DV + l];
        uint2 q2 = Yin[c2 * DV + l];
        uint2 q3 = Yin[c3 * DV + l];
        uint2 q4 = Yin[c4 * DV + l];
        uint2 q5 = Yin[c5 * DV + l];
        uint2 q6 = Yin[c6 * DV + l];
        uint2 q7 = Yin[c7 * DV + l];
        acc4(ax, ay, az, aw, w0, q0);
        acc4(ax, ay, az, aw, w1, q1);
        acc4(ax, ay, az, aw, w2, q2);
        acc4(ax, ay, az, aw, w3, q3);
        acc4(ax, ay, az, aw, w4, q4);
        acc4(ax, ay, az, aw, w5, q5);
        acc4(ax, ay, az, aw, w6, q6);
        acc4(ax, ay, az, aw, w7, q7);
    }
    for (; s < se; ++s) {
        int c    = g_col[s];
        float wv = HAS_W ? g_w[s] : 1.f;
        acc4(ax, ay, az, aw, wv, Yin[c * DV + l]);
    }

    float rs  = g_rs[v];
    float rx  = g_rx[v];
    float hrs = 0.5f * rs;
    float hrx = 0.5f * rx;
    float4 y = g_Y[t];
    float4 x = X4[t];
    float4 yn;
    yn.x = 0.5f * y.x + hrs * ax + hrx * x.x;
    yn.y = 0.5f * y.y + hrs * ay + hrx * x.y;
    yn.z = 0.5f * y.z + hrs * az + hrx * x.z;
    yn.w = 0.5f * y.w + hrs * aw + hrx * x.w;

    if (TO_OUT) outp[t] = yn; else g_Y[t] = yn;
    if (WRITE_YS) Yso[t] = pack4(yn.x * rs, yn.y * rs, yn.z * rs, yn.w * rs);
}

// -------------------------------------------------------------- attention

// Per node: Zv in registers, gather Y[src] (fp32), 16-lane shfl reduction of
// |dZ|^2 with the group mask (two nodes share a warp; trip counts differ).
// Lane 0 computes w and weighted degree. Fused rescale: new rs/rx and
// YsA = rs_new * Y (operand for step 4).
__global__ void __launch_bounds__(256)
k_attn(const float4* __restrict__ etas4, int N) {
    int t = blockIdx.x * 256 + threadIdx.x;
    int v = t >> 4;
    if (v >= N) return;
    int l = t & 15;
    unsigned mask = 0xFFFFu << (threadIdx.x & 16);

    float4 et = etas4[l];
    float4 yv = g_Y[t];
    float4 zv = make_float4(yv.x * et.x, yv.y * et.y, yv.z * et.z, yv.w * et.w);

    float degw = 0.f;
    int se = g_rowptr[v + 1];
    for (int s = g_rowptr[v]; s < se; ++s) {
        int c     = g_col[s];
        float4 yc = g_Y[c * DV + l];
        float dx = zv.x - yc.x * et.x;
        float dy = zv.y - yc.y * et.y;
        float dz = zv.z - yc.z * et.z;
        float dw = zv.w - yc.w * et.w;
        float p = dx * dx + dy * dy + dz * dz + dw * dw;
        p += __shfl_xor_sync(mask, p, 8);
        p += __shfl_xor_sync(mask, p, 4);
        p += __shfl_xor_sync(mask, p, 2);
        p += __shfl_xor_sync(mask, p, 1);
        if (l == 0) {
            float wv = (p > 2.0f) ? 0.2f : 0.5f / sqrtf(p + 1e-7f);
            g_w[s] = wv;
            degw  += wv;
        }
    }
    // fused rescale: broadcast degw from lane 0 of each 16-lane group
    float deg = __shfl_sync(0xFFFFFFFFu, degw, 0, 16);
    float rs  = 1.0f / sqrtf(deg + 1.0f);
    if (l == 0) { g_rs[v] = rs; g_rx[v] = 1.0f / (deg + 1.0f); }
    g_YsA[t] = pack4(yv.x * rs, yv.y * rs, yv.z * rs, yv.w * rs);
}

// -------------------------------------------------------------- launcher

extern "C" void kernel_launch(void* const* d_in, const int* in_sizes, int n_in,
                              void* d_out, int out_size) {
    const float4* X4    = (const float4*)d_in[0];
    const float4* etas4 = (const float4*)d_in[1];
    const int*    src   = (const int*)d_in[2];
    const int*    dst   = (const int*)d_in[3];
    float4*       out4  = (float4*)d_out;

    int N = in_sizes[0] / 64;
    int E = in_sizes[2];

    int bN  = (N + 255) / 256;
    int bE  = (E + 255) / 256;
    int NB  = (N + 1023) / 1024;
    int bT  = (N * DV + 255) / 256;

    // ---- CSR build (5 kernels; scan is single-pass lookback) ----
    k_zero<<<bN, 256>>>(N);
    k_count<<<bE, 256>>>(dst, E);
    k_scanlb<<<NB, 1024>>>(N, E);
    k_scatter<<<bE, 256>>>(src, dst, E);
    k_init<<<bT, 256>>>(X4, N);

    // ---- steps 0..3: w == 1 ----
    k_agg<false, true,  false><<<bT, 256>>>(X4, out4, 0, N);
    k_agg<false, true,  false><<<bT, 256>>>(X4, out4, 1, N);
    k_agg<false, true,  false><<<bT, 256>>>(X4, out4, 0, N);
    k_agg<false, false, false><<<bT, 256>>>(X4, out4, 1, N);

    // ---- attention after round 4 (rescale fused) ----
    k_attn<<<bT, 256>>>(etas4, N);

    // ---- steps 4..7: attention weights ----
    k_agg<true, true,  false><<<bT, 256>>>(X4, out4, 0, N);
    k_agg<true, true,  false><<<bT, 256>>>(X4, out4, 1, N);
    k_agg<true, true,  false><<<bT, 256>>>(X4, out4, 0, N);
    k_agg<true, false, true ><<<bT, 256>>>(X4, out4, 1, N);
}

// round 13
// speedup vs baseline: 1.0469x; 1.0329x over previous
#include <cuda_runtime.h>
#include <cuda_fp16.h>

// ---------------------------------------------------------------------------
// UnfoldindAndAttention: 8 rounds of normalized graph propagation,
// N=50000, D=64, E=1.6M, attention reweighting after round 4.
// Pull-based CSR (grouped by dst): no float atomics, L2-resident.
// R13 = R7 EXACTLY (fp16 agg operand, 8-wide gather, fp32 attention with
//       fused rescale, 3-kernel scan — best measured 323.7us)
//       + atomic-free scatter: k_count's atomicAdd return value IS the
//         within-row offset; record it (g_eoff) so k_scatter is a pure
//         gather+write with no cursor atomics (ncu: scatter was 29us).
// ---------------------------------------------------------------------------

#define NMAX 50048
#define EMAX 1600000
#define DV   16          // 64 floats = 16 float4 (or 16 uint2 fp16) per node row

static __device__ int    g_cnt[NMAX];
static __device__ int    g_rowptr[NMAX + 1];
static __device__ int    g_bsum[256];
static __device__ int    g_boff[256];
static __device__ int    g_eoff[EMAX];         // within-row offset per edge
static __device__ int    g_col[EMAX];          // src index per CSR slot
static __device__ float  g_w[EMAX];            // attention weight per CSR slot
static __device__ float  g_rs[NMAX];           // (deg+1)^-0.5
static __device__ float  g_rx[NMAX];           // (deg+1)^-1
static __device__ float4 g_Y[NMAX * DV];       // current Y (fp32)
static __device__ uint2  g_YsA[NMAX * DV];     // rs*Y in fp16 ping
static __device__ uint2  g_YsB[NMAX * DV];     // pong

// -------------------------------------------------------------- setup kernels

__global__ void k_zero(int N) {
    int i = blockIdx.x * 256 + threadIdx.x;
    if (i < N) g_cnt[i] = 0;
}

// count in-degrees AND record each edge's within-row slot (atomic return)
__global__ void k_count(const int* __restrict__ dst, int E) {
    int e = blockIdx.x * 256 + threadIdx.x;
    if (e < E) g_eoff[e] = atomicAdd(&g_cnt[dst[e]], 1);
}

// Exclusive block scan (blockDim = 1024). mode 0: cnt -> rowptr (+bsum),
// mode 1: bsum -> boff.
__global__ void k_scan(int mode, int n) {
    const int* in = mode ? g_bsum : g_cnt;
    int* out      = mode ? g_boff : g_rowptr;
    __shared__ int ws[32];
    int g    = blockIdx.x * 1024 + threadIdx.x;
    int lane = threadIdx.x & 31;
    int wid  = threadIdx.x >> 5;
    int v = (g < n) ? in[g] : 0;
    int x = v;
#pragma unroll
    for (int o = 1; o < 32; o <<= 1) {
        int y = __shfl_up_sync(0xFFFFFFFFu, x, o);
        if (lane >= o) x += y;
    }
    if (lane == 31) ws[wid] = x;
    __syncthreads();
    if (wid == 0) {
        int s = ws[lane];
#pragma unroll
        for (int o = 1; o < 32; o <<= 1) {
            int y = __shfl_up_sync(0xFFFFFFFFu, s, o);
            if (lane >= o) s += y;
        }
        ws[lane] = s;
    }
    __syncthreads();
    int boff = wid ? ws[wid - 1] : 0;
    if (g < n) out[g] = boff + x - v;          // exclusive
    if (mode == 0 && threadIdx.x == 0) g_bsum[blockIdx.x] = ws[31];
}

__global__ void k_addoff(int n, int E) {
    int g = blockIdx.x * 1024 + threadIdx.x;
    if (g < n) g_rowptr[g] += g_boff[blockIdx.x];
    if (blockIdx.x == 0 && threadIdx.x == 0) g_rowptr[n] = E;
}

// atomic-free scatter: slot was precomputed in k_count
__global__ void k_scatter(const int* __restrict__ src, const int* __restrict__ dst, int E) {
    int e = blockIdx.x * 256 + threadIdx.x;
    if (e < E) {
        int v = dst[e];
        g_col[g_rowptr[v] + g_eoff[e]] = src[e];
    }
}

static __device__ __forceinline__ uint2 pack4(float a, float b, float c, float d) {
    half2 h0 = __floats2half2_rn(a, b);
    half2 h1 = __floats2half2_rn(c, d);
    uint2 r;
    r.x = *(unsigned int*)&h0;
    r.y = *(unsigned int*)&h1;
    return r;
}

// Y0 = X; rs/rx from integer in-degree; YsA = fp16(rs * X)
__global__ void k_init(const float4* __restrict__ X4, int N) {
    int t = blockIdx.x * 256 + threadIdx.x;
    if (t >= N * DV) return;
    int v = t >> 4;
    float deg = (float)g_cnt[v];
    float rs  = 1.0f / sqrtf(deg + 1.0f);
    if ((t & 15) == 0) { g_rs[v] = rs; g_rx[v] = 1.0f / (deg + 1.0f); }
    float4 x = X4[t];
    g_Y[t]   = x;
    g_YsA[t] = pack4(x.x * rs, x.y * rs, x.z * rs, x.w * rs);
}

// -------------------------------------------------------------- propagation

static __device__ __forceinline__ void acc4(float& ax, float& ay, float& az, float& aw,
                                            float w, uint2 q) {
    float2 f0 = __half22float2(*(half2*)&q.x);
    float2 f1 = __half22float2(*(half2*)&q.y);
    ax = fmaf(w, f0.x, ax);
    ay = fmaf(w, f0.y, ay);
    az = fmaf(w, f1.x, az);
    aw = fmaf(w, f1.y, aw);
}

// One propagation step, fused: pull-aggregate + epilogue + next-step operand.
// Half-warp (16 lanes, 4 features each) per node. 8 gathers in flight.
template<bool HAS_W, bool WRITE_YS, bool TO_OUT>
__global__ void __launch_bounds__(256)
k_agg(const float4* __restrict__ X4, float4* __restrict__ outp, int par, int N) {
    int t = blockIdx.x * 256 + threadIdx.x;
    int v = t >> 4;
    if (v >= N) return;
    int l = t & 15;
    const uint2* __restrict__ Yin = par ? g_YsB : g_YsA;
    uint2* Yso                    = par ? g_YsA : g_YsB;

    int s  = g_rowptr[v];
    int se = g_rowptr[v + 1];
    float ax = 0.f, ay = 0.f, az = 0.f, aw = 0.f;

    for (; s + 8 <= se; s += 8) {
        int c0 = g_col[s],     c1 = g_col[s + 1], c2 = g_col[s + 2], c3 = g_col[s + 3];
        int c4 = g_col[s + 4], c5 = g_col[s + 5], c6 = g_col[s + 6], c7 = g_col[s + 7];
        float w0 = 1.f, w1 = 1.f, w2 = 1.f, w3 = 1.f;
        float w4 = 1.f, w5 = 1.f, w6 = 1.f, w7 = 1.f;
        if (HAS_W) {
            w0 = g_w[s];     w1 = g_w[s + 1]; w2 = g_w[s + 2]; w3 = g_w[s + 3];
            w4 = g_w[s + 4]; w5 = g_w[s + 5]; w6 = g_w[s + 6]; w7 = g_w[s + 7];
        }
        uint2 q0 = Yin[c0 * DV + l];
        uint2 q1 = Yin[c1 * DV + l];
        uint2 q2 = Yin[c2 * DV + l];
        uint2 q3 = Yin[c3 * DV + l];
        uint2 q4 = Yin[c4 * DV + l];
        uint2 q5 = Yin[c5 * DV + l];
        uint2 q6 = Yin[c6 * DV + l];
        uint2 q7 = Yin[c7 * DV + l];
        acc4(ax, ay, az, aw, w0, q0);
        acc4(ax, ay, az, aw, w1, q1);
        acc4(ax, ay, az, aw, w2, q2);
        acc4(ax, ay, az, aw, w3, q3);
        acc4(ax, ay, az, aw, w4, q4);
        acc4(ax, ay, az, aw, w5, q5);
        acc4(ax, ay, az, aw, w6, q6);
        acc4(ax, ay, az, aw, w7, q7);
    }
    for (; s < se; ++s) {
        int c    = g_col[s];
        float wv = HAS_W ? g_w[s] : 1.f;
        acc4(ax, ay, az, aw, wv, Yin[c * DV + l]);
    }

    float rs  = g_rs[v];
    float rx  = g_rx[v];
    float hrs = 0.5f * rs;
    float hrx = 0.5f * rx;
    float4 y = g_Y[t];
    float4 x = X4[t];
    float4 yn;
    yn.x = 0.5f * y.x + hrs * ax + hrx * x.x;
    yn.y = 0.5f * y.y + hrs * ay + hrx * x.y;
    yn.z = 0.5f * y.z + hrs * az + hrx * x.z;
    yn.w = 0.5f * y.w + hrs * aw + hrx * x.w;

    if (TO_OUT) outp[t] = yn; else g_Y[t] = yn;
    if (WRITE_YS) Yso[t] = pack4(yn.x * rs, yn.y * rs, yn.z * rs, yn.w * rs);
}

// -------------------------------------------------------------- attention

// Per node: Zv in registers, gather Y[src] (fp32), 16-lane shfl reduction of
// |dZ|^2 with the group mask (two nodes share a warp; trip counts differ).
// Lane 0 computes w and weighted degree. Fused rescale: new rs/rx and
// YsA = rs_new * Y (operand for step 4).
__global__ void __launch_bounds__(256)
k_attn(const float4* __restrict__ etas4, int N) {
    int t = blockIdx.x * 256 + threadIdx.x;
    int v = t >> 4;
    if (v >= N) return;
    int l = t & 15;
    unsigned mask = 0xFFFFu << (threadIdx.x & 16);

    float4 et = etas4[l];
    float4 yv = g_Y[t];
    float4 zv = make_float4(yv.x * et.x, yv.y * et.y, yv.z * et.z, yv.w * et.w);

    float degw = 0.f;
    int se = g_rowptr[v + 1];
    for (int s = g_rowptr[v]; s < se; ++s) {
        int c     = g_col[s];
        float4 yc = g_Y[c * DV + l];
        float dx = zv.x - yc.x * et.x;
        float dy = zv.y - yc.y * et.y;
        float dz = zv.z - yc.z * et.z;
        float dw = zv.w - yc.w * et.w;
        float p = dx * dx + dy * dy + dz * dz + dw * dw;
        p += __shfl_xor_sync(mask, p, 8);
        p += __shfl_xor_sync(mask, p, 4);
        p += __shfl_xor_sync(mask, p, 2);
        p += __shfl_xor_sync(mask, p, 1);
        if (l == 0) {
            float wv = (p > 2.0f) ? 0.2f : 0.5f / sqrtf(p + 1e-7f);
            g_w[s] = wv;
            degw  += wv;
        }
    }
    // fused rescale: broadcast degw from lane 0 of each 16-lane group
    float deg = __shfl_sync(0xFFFFFFFFu, degw, 0, 16);
    float rs  = 1.0f / sqrtf(deg + 1.0f);
    if (l == 0) { g_rs[v] = rs; g_rx[v] = 1.0f / (deg + 1.0f); }
    g_YsA[t] = pack4(yv.x * rs, yv.y * rs, yv.z * rs, yv.w * rs);
}

// -------------------------------------------------------------- launcher

extern "C" void kernel_launch(void* const* d_in, const int* in_sizes, int n_in,
                              void* d_out, int out_size) {
    const float4* X4    = (const float4*)d_in[0];
    const float4* etas4 = (const float4*)d_in[1];
    const int*    src   = (const int*)d_in[2];
    const int*    dst   = (const int*)d_in[3];
    float4*       out4  = (float4*)d_out;

    int N = in_sizes[0] / 64;
    int E = in_sizes[2];

    int bN  = (N + 255) / 256;
    int bE  = (E + 255) / 256;
    int NB  = (N + 1023) / 1024;
    int bT  = (N * DV + 255) / 256;

    // ---- CSR build ----
    k_zero<<<bN, 256>>>(N);
    k_count<<<bE, 256>>>(dst, E);
    k_scan<<<NB, 1024>>>(0, N);
    k_scan<<<1, 1024>>>(1, NB);
    k_addoff<<<NB, 1024>>>(N, E);
    k_scatter<<<bE, 256>>>(src, dst, E);
    k_init<<<bT, 256>>>(X4, N);

    // ---- steps 0..3: w == 1 ----
    k_agg<false, true,  false><<<bT, 256>>>(X4, out4, 0, N);
    k_agg<false, true,  false><<<bT, 256>>>(X4, out4, 1, N);
    k_agg<false, true,  false><<<bT, 256>>>(X4, out4, 0, N);
    k_agg<false, false, false><<<bT, 256>>>(X4, out4, 1, N);

    // ---- attention after round 4 (rescale fused) ----
    k_attn<<<bT, 256>>>(etas4, N);

    // ---- steps 4..7: attention weights ----
    k_agg<true, true,  false><<<bT, 256>>>(X4, out4, 0, N);
    k_agg<true, true,  false><<<bT, 256>>>(X4, out4, 1, N);
    k_agg<true, true,  false><<<bT, 256>>>(X4, out4, 0, N);
    k_agg<true, false, true ><<<bT, 256>>>(X4, out4, 1, N);
}

// round 14
// speedup vs baseline: 1.0596x; 1.0122x over previous
#include <cuda_runtime.h>
#include <cuda_fp16.h>

// ---------------------------------------------------------------------------
// UnfoldindAndAttention: 8 rounds of normalized graph propagation,
// N=50000, D=64, E=1.6M, attention reweighting after round 4.
// Pull-based CSR (grouped by dst): no float atomics, L2-resident.
// R14 = R13 (best: 319.5us) with setup compressed 7 -> 5 kernels:
//   - k_addoff scans g_bsum itself (drops the 1-block k_scan launch, 4.5us)
//   - k_zero dropped: statics are zero-init at load; k_init re-zeroes g_cnt
//     after consuming it, restoring the entry invariant for every call.
// Mainloop is R7/R13 verbatim; numerics bit-identical.
// ---------------------------------------------------------------------------

#define NMAX 50048
#define EMAX 1600000
#define DV   16          // 64 floats = 16 float4 (or 16 uint2 fp16) per node row

static __device__ int    g_cnt[NMAX];          // zero at load; re-zeroed by k_init
static __device__ int    g_rowptr[NMAX + 1];
static __device__ int    g_bsum[256];
static __device__ int    g_eoff[EMAX];         // within-row offset per edge
static __device__ int    g_col[EMAX];          // src index per CSR slot
static __device__ float  g_w[EMAX];            // attention weight per CSR slot
static __device__ float  g_rs[NMAX];           // (deg+1)^-0.5
static __device__ float  g_rx[NMAX];           // (deg+1)^-1
static __device__ float4 g_Y[NMAX * DV];       // current Y (fp32)
static __device__ uint2  g_YsA[NMAX * DV];     // rs*Y in fp16 ping
static __device__ uint2  g_YsB[NMAX * DV];     // pong

// -------------------------------------------------------------- setup kernels

// count in-degrees AND record each edge's within-row slot (atomic return).
// g_cnt is zero on entry (load-time init / re-zeroed by k_init last call).
__global__ void k_count(const int* __restrict__ dst, int E) {
    int e = blockIdx.x * 256 + threadIdx.x;
    if (e < E) g_eoff[e] = atomicAdd(&g_cnt[dst[e]], 1);
}

// Exclusive block scan of g_cnt -> g_rowptr (partial, per-block) + g_bsum.
__global__ void k_scan(int n) {
    __shared__ int ws[32];
    int g    = blockIdx.x * 1024 + threadIdx.x;
    int lane = threadIdx.x & 31;
    int wid  = threadIdx.x >> 5;
    int v = (g < n) ? g_cnt[g] : 0;
    int x = v;
#pragma unroll
    for (int o = 1; o < 32; o <<= 1) {
        int y = __shfl_up_sync(0xFFFFFFFFu, x, o);
        if (lane >= o) x += y;
    }
    if (lane == 31) ws[wid] = x;
    __syncthreads();
    if (wid == 0) {
        int s = ws[lane];
#pragma unroll
        for (int o = 1; o < 32; o <<= 1) {
            int y = __shfl_up_sync(0xFFFFFFFFu, s, o);
            if (lane >= o) s += y;
        }
        ws[lane] = s;
    }
    __syncthreads();
    int boff = wid ? ws[wid - 1] : 0;
    if (g < n) g_rowptr[g] = boff + x - v;     // block-local exclusive
    if (threadIdx.x == 0) g_bsum[blockIdx.x] = ws[31];
}

// add cross-block offsets; each block computes its own prefix over g_bsum
// (<= 256 blocks; 32-lane strided reduce).
__global__ void k_addoff(int n, int E) {
    __shared__ int spfx;
    if (threadIdx.x < 32) {
        int s = 0;
        for (int p = threadIdx.x; p < blockIdx.x; p += 32) s += g_bsum[p];
#pragma unroll
        for (int o = 16; o; o >>= 1) s += __shfl_xor_sync(0xFFFFFFFFu, s, o);
        if (threadIdx.x == 0) spfx = s;
    }
    __syncthreads();
    int g = blockIdx.x * 1024 + threadIdx.x;
    if (g < n) g_rowptr[g] += spfx;
    if (g == 0) g_rowptr[n] = E;
}

// atomic-free scatter: slot was precomputed in k_count
__global__ void k_scatter(const int* __restrict__ src, const int* __restrict__ dst, int E) {
    int e = blockIdx.x * 256 + threadIdx.x;
    if (e < E) {
        int v = dst[e];
        g_col[g_rowptr[v] + g_eoff[e]] = src[e];
    }
}

static __device__ __forceinline__ uint2 pack4(float a, float b, float c, float d) {
    half2 h0 = __floats2half2_rn(a, b);
    half2 h1 = __floats2half2_rn(c, d);
    uint2 r;
    r.x = *(unsigned int*)&h0;
    r.y = *(unsigned int*)&h1;
    return r;
}

// Y0 = X; rs/rx from integer in-degree; YsA = fp16(rs * X).
// Re-zeroes g_cnt (last reader) so the next kernel_launch call sees zeros.
__global__ void k_init(const float4* __restrict__ X4, int N) {
    int t = blockIdx.x * 256 + threadIdx.x;
    if (t >= N * DV) return;
    int v = t >> 4;
    float deg = (float)g_cnt[v];
    float rs  = 1.0f / sqrtf(deg + 1.0f);
    if ((t & 15) == 0) { g_rs[v] = rs; g_rx[v] = 1.0f / (deg + 1.0f); g_cnt[v] = 0; }
    float4 x = X4[t];
    g_Y[t]   = x;
    g_YsA[t] = pack4(x.x * rs, x.y * rs, x.z * rs, x.w * rs);
}

// -------------------------------------------------------------- propagation

static __device__ __forceinline__ void acc4(float& ax, float& ay, float& az, float& aw,
                                            float w, uint2 q) {
    float2 f0 = __half22float2(*(half2*)&q.x);
    float2 f1 = __half22float2(*(half2*)&q.y);
    ax = fmaf(w, f0.x, ax);
    ay = fmaf(w, f0.y, ay);
    az = fmaf(w, f1.x, az);
    aw = fmaf(w, f1.y, aw);
}

// One propagation step, fused: pull-aggregate + epilogue + next-step operand.
// Half-warp (16 lanes, 4 features each) per node. 8 gathers in flight.
template<bool HAS_W, bool WRITE_YS, bool TO_OUT>
__global__ void __launch_bounds__(256)
k_agg(const float4* __restrict__ X4, float4* __restrict__ outp, int par, int N) {
    int t = blockIdx.x * 256 + threadIdx.x;
    int v = t >> 4;
    if (v >= N) return;
    int l = t & 15;
    const uint2* __restrict__ Yin = par ? g_YsB : g_YsA;
    uint2* Yso                    = par ? g_YsA : g_YsB;

    int s  = g_rowptr[v];
    int se = g_rowptr[v + 1];
    float ax = 0.f, ay = 0.f, az = 0.f, aw = 0.f;

    for (; s + 8 <= se; s += 8) {
        int c0 = g_col[s],     c1 = g_col[s + 1], c2 = g_col[s + 2], c3 = g_col[s + 3];
        int c4 = g_col[s + 4], c5 = g_col[s + 5], c6 = g_col[s + 6], c7 = g_col[s + 7];
        float w0 = 1.f, w1 = 1.f, w2 = 1.f, w3 = 1.f;
        float w4 = 1.f, w5 = 1.f, w6 = 1.f, w7 = 1.f;
        if (HAS_W) {
            w0 = g_w[s];     w1 = g_w[s + 1]; w2 = g_w[s + 2]; w3 = g_w[s + 3];
            w4 = g_w[s + 4]; w5 = g_w[s + 5]; w6 = g_w[s + 6]; w7 = g_w[s + 7];
        }
        uint2 q0 = Yin[c0 * DV + l];
        uint2 q1 = Yin[c1 * DV + l];
        uint2 q2 = Yin[c2 * DV + l];
        uint2 q3 = Yin[c3 * DV + l];
        uint2 q4 = Yin[c4 * DV + l];
        uint2 q5 = Yin[c5 * DV + l];
        uint2 q6 = Yin[c6 * DV + l];
        uint2 q7 = Yin[c7 * DV + l];
        acc4(ax, ay, az, aw, w0, q0);
        acc4(ax, ay, az, aw, w1, q1);
        acc4(ax, ay, az, aw, w2, q2);
        acc4(ax, ay, az, aw, w3, q3);
        acc4(ax, ay, az, aw, w4, q4);
        acc4(ax, ay, az, aw, w5, q5);
        acc4(ax, ay, az, aw, w6, q6);
        acc4(ax, ay, az, aw, w7, q7);
    }
    for (; s < se; ++s) {
        int c    = g_col[s];
        float wv = HAS_W ? g_w[s] : 1.f;
        acc4(ax, ay, az, aw, wv, Yin[c * DV + l]);
    }

    float rs  = g_rs[v];
    float rx  = g_rx[v];
    float hrs = 0.5f * rs;
    float hrx = 0.5f * rx;
    float4 y = g_Y[t];
    float4 x = X4[t];
    float4 yn;
    yn.x = 0.5f * y.x + hrs * ax + hrx * x.x;
    yn.y = 0.5f * y.y + hrs * ay + hrx * x.y;
    yn.z = 0.5f * y.z + hrs * az + hrx * x.z;
    yn.w = 0.5f * y.w + hrs * aw + hrx * x.w;

    if (TO_OUT) outp[t] = yn; else g_Y[t] = yn;
    if (WRITE_YS) Yso[t] = pack4(yn.x * rs, yn.y * rs, yn.z * rs, yn.w * rs);
}

// -------------------------------------------------------------- attention

// Per node: Zv in registers, gather Y[src] (fp32), 16-lane shfl reduction of
// |dZ|^2 with the group mask (two nodes share a warp; trip counts differ).
// Lane 0 computes w and weighted degree. Fused rescale: new rs/rx and
// YsA = rs_new * Y (operand for step 4).
__global__ void __launch_bounds__(256)
k_attn(const float4* __restrict__ etas4, int N) {
    int t = blockIdx.x * 256 + threadIdx.x;
    int v = t >> 4;
    if (v >= N) return;
    int l = t & 15;
    unsigned mask = 0xFFFFu << (threadIdx.x & 16);

    float4 et = etas4[l];
    float4 yv = g_Y[t];
    float4 zv = make_float4(yv.x * et.x, yv.y * et.y, yv.z * et.z, yv.w * et.w);

    float degw = 0.f;
    int se = g_rowptr[v + 1];
    for (int s = g_rowptr[v]; s < se; ++s) {
        int c     = g_col[s];
        float4 yc = g_Y[c * DV + l];
        float dx = zv.x - yc.x * et.x;
        float dy = zv.y - yc.y * et.y;
        float dz = zv.z - yc.z * et.z;
        float dw = zv.w - yc.w * et.w;
        float p = dx * dx + dy * dy + dz * dz + dw * dw;
        p += __shfl_xor_sync(mask, p, 8);
        p += __shfl_xor_sync(mask, p, 4);
        p += __shfl_xor_sync(mask, p, 2);
        p += __shfl_xor_sync(mask, p, 1);
        if (l == 0) {
            float wv = (p > 2.0f) ? 0.2f : 0.5f / sqrtf(p + 1e-7f);
            g_w[s] = wv;
            degw  += wv;
        }
    }
    // fused rescale: broadcast degw from lane 0 of each 16-lane group
    float deg = __shfl_sync(0xFFFFFFFFu, degw, 0, 16);
    float rs  = 1.0f / sqrtf(deg + 1.0f);
    if (l == 0) { g_rs[v] = rs; g_rx[v] = 1.0f / (deg + 1.0f); }
    g_YsA[t] = pack4(yv.x * rs, yv.y * rs, yv.z * rs, yv.w * rs);
}

// -------------------------------------------------------------- launcher

extern "C" void kernel_launch(void* const* d_in, const int* in_sizes, int n_in,
                              void* d_out, int out_size) {
    const float4* X4    = (const float4*)d_in[0];
    const float4* etas4 = (const float4*)d_in[1];
    const int*    src   = (const int*)d_in[2];
    const int*    dst   = (const int*)d_in[3];
    float4*       out4  = (float4*)d_out;

    int N = in_sizes[0] / 64;
    int E = in_sizes[2];

    int bE  = (E + 255) / 256;
    int NB  = (N + 1023) / 1024;
    int bT  = (N * DV + 255) / 256;

    // ---- CSR build (5 kernels) ----
    k_count<<<bE, 256>>>(dst, E);
    k_scan<<<NB, 1024>>>(N);
    k_addoff<<<NB, 1024>>>(N, E);
    k_scatter<<<bE, 256>>>(src, dst, E);
    k_init<<<bT, 256>>>(X4, N);

    // ---- steps 0..3: w == 1 ----
    k_agg<false, true,  false><<<bT, 256>>>(X4, out4, 0, N);
    k_agg<false, true,  false><<<bT, 256>>>(X4, out4, 1, N);
    k_agg<false, true,  false><<<bT, 256>>>(X4, out4, 0, N);
    k_agg<false, false, false><<<bT, 256>>>(X4, out4, 1, N);

    // ---- attention after round 4 (rescale fused) ----
    k_attn<<<bT, 256>>>(etas4, N);

    // ---- steps 4..7: attention weights ----
    k_agg<true, true,  false><<<bT, 256>>>(X4, out4, 0, N);
    k_agg<true, true,  false><<<bT, 256>>>(X4, out4, 1, N);
    k_agg<true, true,  false><<<bT, 256>>>(X4, out4, 0, N);
    k_agg<true, false, true ><<<bT, 256>>>(X4, out4, 1, N);
}

// round 17
// speedup vs baseline: 1.0601x; 1.0005x over previous
#include <cuda_runtime.h>
#include <cuda_fp16.h>

// ---------------------------------------------------------------------------
// UnfoldindAndAttention: 8 rounds of normalized graph propagation,
// N=50000, D=64, E=1.6M, attention reweighting after round 4.
// Pull-based CSR (grouped by dst): no float atomics, L2-resident.
// R17 = R14 (last passing: 315.7us) + packed (dst:hi16|eoff:lo16) stream
//       so k_scatter reads one 6.4MB array instead of two.
// The R15 arrive-spin scan is ABANDONED: two consecutive container failures
// point at the cross-launch spin state being incompatible with kernel-level
// replay (ncu -c 1 replays k_scanf in isolation; the g_arrive reset lives in
// a later kernel, so an isolated replay can hang). All kernels here are
// idempotent given their inputs -> replay-safe.
// Mainloop is R7/R13 verbatim; numerics bit-identical.
// ---------------------------------------------------------------------------

#define NMAX 50048
#define EMAX 1600000
#define DV   16          // 64 floats = 16 float4 (or 16 uint2 fp16) per node row

static __device__ int          g_cnt[NMAX];    // zero at load; re-zeroed by k_init
static __device__ int          g_rowptr[NMAX + 1];
static __device__ int          g_bsum[256];
static __device__ unsigned int g_dstoff[EMAX]; // (dst<<16) | within-row offset
static __device__ int          g_col[EMAX];    // src index per CSR slot
static __device__ float        g_w[EMAX];      // attention weight per CSR slot
static __device__ float        g_rs[NMAX];     // (deg+1)^-0.5
static __device__ float        g_rx[NMAX];     // (deg+1)^-1
static __device__ float4       g_Y[NMAX * DV]; // current Y (fp32)
static __device__ uint2        g_YsA[NMAX * DV]; // rs*Y in fp16 ping
static __device__ uint2        g_YsB[NMAX * DV]; // pong

// -------------------------------------------------------------- setup kernels

// count in-degrees AND record (dst | within-row slot) packed (atomic return).
// g_cnt is zero on entry (load-time init / re-zeroed by k_init last call).
__global__ void k_count(const int* __restrict__ dst, int E) {
    int e = blockIdx.x * 256 + threadIdx.x;
    if (e < E) {
        int v = dst[e];
        int off = atomicAdd(&g_cnt[v], 1);
        g_dstoff[e] = ((unsigned int)v << 16) | (unsigned int)off;
    }
}

// Exclusive block scan of g_cnt -> g_rowptr (partial, per-block) + g_bsum.
__global__ void k_scan(int n) {
    __shared__ int ws[32];
    int g    = blockIdx.x * 1024 + threadIdx.x;
    int lane = threadIdx.x & 31;
    int wid  = threadIdx.x >> 5;
    int v = (g < n) ? g_cnt[g] : 0;
    int x = v;
#pragma unroll
    for (int o = 1; o < 32; o <<= 1) {
        int y = __shfl_up_sync(0xFFFFFFFFu, x, o);
        if (lane >= o) x += y;
    }
    if (lane == 31) ws[wid] = x;
    __syncthreads();
    if (wid == 0) {
        int s = ws[lane];
#pragma unroll
        for (int o = 1; o < 32; o <<= 1) {
            int y = __shfl_up_sync(0xFFFFFFFFu, s, o);
            if (lane >= o) s += y;
        }
        ws[lane] = s;
    }
    __syncthreads();
    int boff = wid ? ws[wid - 1] : 0;
    if (g < n) g_rowptr[g] = boff + x - v;     // block-local exclusive
    if (threadIdx.x == 0) g_bsum[blockIdx.x] = ws[31];
}

// add cross-block offsets; each block computes its own prefix over g_bsum
// (<= 256 blocks; 32-lane strided reduce).
__global__ void k_addoff(int n, int E) {
    __shared__ int spfx;
    if (threadIdx.x < 32) {
        int s = 0;
        for (int p = threadIdx.x; p < blockIdx.x; p += 32) s += g_bsum[p];
#pragma unroll
        for (int o = 16; o; o >>= 1) s += __shfl_xor_sync(0xFFFFFFFFu, s, o);
        if (threadIdx.x == 0) spfx = s;
    }
    __syncthreads();
    int g = blockIdx.x * 1024 + threadIdx.x;
    if (g < n) g_rowptr[g] += spfx;
    if (g == 0) g_rowptr[n] = E;
}

// atomic-free scatter: dst and slot come from one packed stream
__global__ void k_scatter(const int* __restrict__ src, int E) {
    int e = blockIdx.x * 256 + threadIdx.x;
    if (e < E) {
        unsigned int d = g_dstoff[e];
        g_col[g_rowptr[d >> 16] + (d & 0xFFFFu)] = src[e];
    }
}

static __device__ __forceinline__ uint2 pack4(float a, float b, float c, float d) {
    half2 h0 = __floats2half2_rn(a, b);
    half2 h1 = __floats2half2_rn(c, d);
    uint2 r;
    r.x = *(unsigned int*)&h0;
    r.y = *(unsigned int*)&h1;
    return r;
}

// Y0 = X; rs/rx from integer in-degree; YsA = fp16(rs * X).
// Re-zeroes g_cnt (last reader) so the next kernel_launch call sees zeros.
__global__ void k_init(const float4* __restrict__ X4, int N) {
    int t = blockIdx.x * 256 + threadIdx.x;
    if (t >= N * DV) return;
    int v = t >> 4;
    float deg = (float)g_cnt[v];
    float rs  = 1.0f / sqrtf(deg + 1.0f);
    if ((t & 15) == 0) { g_rs[v] = rs; g_rx[v] = 1.0f / (deg + 1.0f); g_cnt[v] = 0; }
    float4 x = X4[t];
    g_Y[t]   = x;
    g_YsA[t] = pack4(x.x * rs, x.y * rs, x.z * rs, x.w * rs);
}

// -------------------------------------------------------------- propagation

static __device__ __forceinline__ void acc4(float& ax, float& ay, float& az, float& aw,
                                            float w, uint2 q) {
    float2 f0 = __half22float2(*(half2*)&q.x);
    float2 f1 = __half22float2(*(half2*)&q.y);
    ax = fmaf(w, f0.x, ax);
    ay = fmaf(w, f0.y, ay);
    az = fmaf(w, f1.x, az);
    aw = fmaf(w, f1.y, aw);
}

// One propagation step, fused: pull-aggregate + epilogue + next-step operand.
// Half-warp (16 lanes, 4 features each) per node. 8 gathers in flight.
template<bool HAS_W, bool WRITE_YS, bool TO_OUT>
__global__ void __launch_bounds__(256)
k_agg(const float4* __restrict__ X4, float4* __restrict__ outp, int par, int N) {
    int t = blockIdx.x * 256 + threadIdx.x;
    int v = t >> 4;
    if (v >= N) return;
    int l = t & 15;
    const uint2* __restrict__ Yin = par ? g_YsB : g_YsA;
    uint2* Yso                    = par ? g_YsA : g_YsB;

    int s  = g_rowptr[v];
    int se = g_rowptr[v + 1];
    float ax = 0.f, ay = 0.f, az = 0.f, aw = 0.f;

    for (; s + 8 <= se; s += 8) {
        int c0 = g_col[s],     c1 = g_col[s + 1], c2 = g_col[s + 2], c3 = g_col[s + 3];
        int c4 = g_col[s + 4], c5 = g_col[s + 5], c6 = g_col[s + 6], c7 = g_col[s + 7];
        float w0 = 1.f, w1 = 1.f, w2 = 1.f, w3 = 1.f;
        float w4 = 1.f, w5 = 1.f, w6 = 1.f, w7 = 1.f;
        if (HAS_W) {
            w0 = g_w[s];     w1 = g_w[s + 1]; w2 = g_w[s + 2]; w3 = g_w[s + 3];
            w4 = g_w[s + 4]; w5 = g_w[s + 5]; w6 = g_w[s + 6]; w7 = g_w[s + 7];
        }
        uint2 q0 = Yin[c0 * DV + l];
        uint2 q1 = Yin[c1 * DV + l];
        uint2 q2 = Yin[c2 * DV + l];
        uint2 q3 = Yin[c3 * DV + l];
        uint2 q4 = Yin[c4 * DV + l];
        uint2 q5 = Yin[c5 * DV + l];
        uint2 q6 = Yin[c6 * DV + l];
        uint2 q7 = Yin[c7 * DV + l];
        acc4(ax, ay, az, aw, w0, q0);
        acc4(ax, ay, az, aw, w1, q1);
        acc4(ax, ay, az, aw, w2, q2);
        acc4(ax, ay, az, aw, w3, q3);
        acc4(ax, ay, az, aw, w4, q4);
        acc4(ax, ay, az, aw, w5, q5);
        acc4(ax, ay, az, aw, w6, q6);
        acc4(ax, ay, az, aw, w7, q7);
    }
    for (; s < se; ++s) {
        int c    = g_col[s];
        float wv = HAS_W ? g_w[s] : 1.f;
        acc4(ax, ay, az, aw, wv, Yin[c * DV + l]);
    }

    float rs  = g_rs[v];
    float rx  = g_rx[v];
    float hrs = 0.5f * rs;
    float hrx = 0.5f * rx;
    float4 y = g_Y[t];
    float4 x = X4[t];
    float4 yn;
    yn.x = 0.5f * y.x + hrs * ax + hrx * x.x;
    yn.y = 0.5f * y.y + hrs * ay + hrx * x.y;
    yn.z = 0.5f * y.z + hrs * az + hrx * x.z;
    yn.w = 0.5f * y.w + hrs * aw + hrx * x.w;

    if (TO_OUT) outp[t] = yn; else g_Y[t] = yn;
    if (WRITE_YS) Yso[t] = pack4(yn.x * rs, yn.y * rs, yn.z * rs, yn.w * rs);
}

// -------------------------------------------------------------- attention

// Per node: Zv in registers, gather Y[src] (fp32), 16-lane shfl reduction of
// |dZ|^2 with the group mask (two nodes share a warp; trip counts differ).
// Lane 0 computes w and weighted degree. Fused rescale: new rs/rx and
// YsA = rs_new * Y (operand for step 4).
__global__ void __launch_bounds__(256)
k_attn(const float4* __restrict__ etas4, int N) {
    int t = blockIdx.x * 256 + threadIdx.x;
    int v = t >> 4;
    if (v >= N) return;
    int l = t & 15;
    unsigned mask = 0xFFFFu << (threadIdx.x & 16);

    float4 et = etas4[l];
    float4 yv = g_Y[t];
    float4 zv = make_float4(yv.x * et.x, yv.y * et.y, yv.z * et.z, yv.w * et.w);

    float degw = 0.f;
    int se = g_rowptr[v + 1];
    for (int s = g_rowptr[v]; s < se; ++s) {
        int c     = g_col[s];
        float4 yc = g_Y[c * DV + l];
        float dx = zv.x - yc.x * et.x;
        float dy = zv.y - yc.y * et.y;
        float dz = zv.z - yc.z * et.z;
        float dw = zv.w - yc.w * et.w;
        float p = dx * dx + dy * dy + dz * dz + dw * dw;
        p += __shfl_xor_sync(mask, p, 8);
        p += __shfl_xor_sync(mask, p, 4);
        p += __shfl_xor_sync(mask, p, 2);
        p += __shfl_xor_sync(mask, p, 1);
        if (l == 0) {
            float wv = (p > 2.0f) ? 0.2f : 0.5f / sqrtf(p + 1e-7f);
            g_w[s] = wv;
            degw  += wv;
        }
    }
    // fused rescale: broadcast degw from lane 0 of each 16-lane group
    float deg = __shfl_sync(0xFFFFFFFFu, degw, 0, 16);
    float rs  = 1.0f / sqrtf(deg + 1.0f);
    if (l == 0) { g_rs[v] = rs; g_rx[v] = 1.0f / (deg + 1.0f); }
    g_YsA[t] = pack4(yv.x * rs, yv.y * rs, yv.z * rs, yv.w * rs);
}

// -------------------------------------------------------------- launcher

extern "C" void kernel_launch(void* const* d_in, const int* in_sizes, int n_in,
                              void* d_out, int out_size) {
    const float4* X4    = (const float4*)d_in[0];
    const float4* etas4 = (const float4*)d_in[1];
    const int*    src   = (const int*)d_in[2];
    const int*    dst   = (const int*)d_in[3];
    float4*       out4  = (float4*)d_out;

    int N = in_sizes[0] / 64;
    int E = in_sizes[2];

    int bE  = (E + 255) / 256;
    int NB  = (N + 1023) / 1024;
    int bT  = (N * DV + 255) / 256;

    // ---- CSR build (5 kernels, all replay-idempotent) ----
    k_count<<<bE, 256>>>(dst, E);
    k_scan<<<NB, 1024>>>(N);
    k_addoff<<<NB, 1024>>>(N, E);
    k_scatter<<<bE, 256>>>(src, E);
    k_init<<<bT, 256>>>(X4, N);

    // ---- steps 0..3: w == 1 ----
    k_agg<false, true,  false><<<bT, 256>>>(X4, out4, 0, N);
    k_agg<false, true,  false><<<bT, 256>>>(X4, out4, 1, N);
    k_agg<false, true,  false><<<bT, 256>>>(X4, out4, 0, N);
    k_agg<false, false, false><<<bT, 256>>>(X4, out4, 1, N);

    // ---- attention after round 4 (rescale fused) ----
    k_attn<<<bT, 256>>>(etas4, N);

    // ---- steps 4..7: attention weights ----
    k_agg<true, true,  false><<<bT, 256>>>(X4, out4, 0, N);
    k_agg<true, true,  false><<<bT, 256>>>(X4, out4, 1, N);
    k_agg<true, true,  false><<<bT, 256>>>(X4, out4, 0, N);
    k_agg<true, false, true ><<<bT, 256>>>(X4, out4, 1, N);
}